// round 3
// baseline (speedup 1.0000x reference)
#include <cuda_runtime.h>
#include <math.h>

// Problem constants
#define B_   64
#define S_   4096
#define ENC_ 512
#define DEC_ 512

#define NCHUNK 16                 // S chunks per batch
#define CHUNK  (S_ / NCHUNK)      // 256 rows per chunk
#define NCTOT  (B_ * NCHUNK)      // 1024 total chunks

// ---- scratch (no allocations allowed; __device__ globals) ----
__device__ float g_sub[B_ * ENC_];          // dec @ W^T            (128 KB)
__device__ float g_logits[B_ * S_];         // raw attention logits (1 MB)
__device__ float g_pm[NCTOT];               // per-chunk running max
__device__ float g_pl[NCTOT];               // per-chunk running denom
__device__ float g_pacc[NCTOT * ENC_];      // per-chunk weighted-sum vec (2 MB)

// ============================================================
// Kernel 1: sub[b,e] = sum_d dec[b,d] * W[e,d]     (tiny GEMV)
// grid = (ENC_/32, B_) = (16, 64) = 1024 CTAs, block = 256 (8 warps)
// Each warp computes 4 e-values -> short serial chains, high parallelism.
// ============================================================
__global__ __launch_bounds__(256) void sub_kernel(const float* __restrict__ dec,
                                                  const float* __restrict__ W) {
    const int et   = blockIdx.x;          // e-tile of 32
    const int b    = blockIdx.y;
    const int tid  = threadIdx.x;
    const int w    = tid >> 5;
    const int lane = tid & 31;

    __shared__ float dsm[DEC_];
    for (int i = tid; i < DEC_; i += 256) dsm[i] = dec[b * DEC_ + i];
    __syncthreads();

    const float4* d4 = (const float4*)dsm;

    // this lane's 16-float slice of dec in registers
    float4 dv[4];
#pragma unroll
    for (int j = 0; j < 4; j++) dv[j] = d4[lane + 32 * j];

    const int e0 = et * 32 + w * 4;       // warp handles e0 .. e0+3
#pragma unroll
    for (int i = 0; i < 4; i++) {
        const int e = e0 + i;
        const float4* Wr = (const float4*)(W + (size_t)e * DEC_);
        float s = 0.f;
#pragma unroll
        for (int j = 0; j < 4; j++) {
            float4 wv = Wr[lane + 32 * j];
            s += wv.x * dv[j].x + wv.y * dv[j].y + wv.z * dv[j].z + wv.w * dv[j].w;
        }
#pragma unroll
        for (int o = 16; o > 0; o >>= 1) s += __shfl_xor_sync(0xffffffffu, s, o);
        if (lane == 0) g_sub[b * ENC_ + e] = s;
    }
}

// ============================================================
// Kernel 2: streaming pass over encoder — logits + online softmax
// grid = (NCHUNK, B_) = (16, 64) = 1024 CTAs, block = 256 (8 warps)
// Warp processes 2 rows per iteration: 8 independent float4 loads in
// flight, two interleaved shuffle reductions, fused 2-row softmax update.
// ============================================================
__global__ __launch_bounds__(256) void attn_pass1(const float* __restrict__ enc) {
    const int c    = blockIdx.x;          // chunk index within batch
    const int b    = blockIdx.y;
    const int tid  = threadIdx.x;
    const int w    = tid >> 5;
    const int lane = tid & 31;

    __shared__ float subsm[ENC_];
    __shared__ float accsm[8][ENC_];      // 16 KB
    __shared__ float msm[8], lsm[8];

    for (int i = tid; i < ENC_; i += 256) subsm[i] = g_sub[b * ENC_ + i];
    __syncthreads();

    // cache this lane's 16-float slice of sub in registers
    float4 subr[4];
    const float4* sub4 = (const float4*)subsm;
#pragma unroll
    for (int j = 0; j < 4; j++) subr[j] = sub4[lane + 32 * j];

    float m = -1e30f;
    float l = 0.f;
    float4 acc[4];
#pragma unroll
    for (int j = 0; j < 4; j++) acc[j] = make_float4(0.f, 0.f, 0.f, 0.f);

    const int s0 = c * CHUNK;
    const float* encb = enc + (size_t)b * S_ * ENC_;

    // two rows per iteration: r1 = s0 + w + 16*it, r2 = r1 + 8
    for (int it = 0; it < CHUNK / 16; it++) {
        const int s1 = s0 + w + 16 * it;
        const int s2 = s1 + 8;
        const float4* er1 = (const float4*)(encb + (size_t)s1 * ENC_);
        const float4* er2 = (const float4*)(encb + (size_t)s2 * ENC_);

        float4 ev1[4], ev2[4];
#pragma unroll
        for (int j = 0; j < 4; j++) ev1[j] = __ldcs(&er1[lane + 32 * j]);
#pragma unroll
        for (int j = 0; j < 4; j++) ev2[j] = __ldcs(&er2[lane + 32 * j]);

        float d1 = 0.f, d2 = 0.f;
#pragma unroll
        for (int j = 0; j < 4; j++) {
            d1 += ev1[j].x * subr[j].x + ev1[j].y * subr[j].y +
                  ev1[j].z * subr[j].z + ev1[j].w * subr[j].w;
            d2 += ev2[j].x * subr[j].x + ev2[j].y * subr[j].y +
                  ev2[j].z * subr[j].z + ev2[j].w * subr[j].w;
        }
#pragma unroll
        for (int o = 16; o > 0; o >>= 1) {
            d1 += __shfl_xor_sync(0xffffffffu, d1, o);
            d2 += __shfl_xor_sync(0xffffffffu, d2, o);
        }

        if (lane == 0)  g_logits[b * S_ + s1] = d1;
        if (lane == 1)  g_logits[b * S_ + s2] = d2;

        // fused 2-row online softmax update (warp-uniform)
        const float mn    = fmaxf(m, fmaxf(d1, d2));
        const float scale = __expf(m - mn);
        const float p1    = __expf(d1 - mn);
        const float p2    = __expf(d2 - mn);
        l = l * scale + p1 + p2;
#pragma unroll
        for (int j = 0; j < 4; j++) {
            acc[j].x = acc[j].x * scale + p1 * ev1[j].x + p2 * ev2[j].x;
            acc[j].y = acc[j].y * scale + p1 * ev1[j].y + p2 * ev2[j].y;
            acc[j].z = acc[j].z * scale + p1 * ev1[j].z + p2 * ev2[j].z;
            acc[j].w = acc[j].w * scale + p1 * ev1[j].w + p2 * ev2[j].w;
        }
        m = mn;
    }

    // spill warp state to smem
    float4* arow = (float4*)accsm[w];
#pragma unroll
    for (int j = 0; j < 4; j++) arow[lane + 32 * j] = acc[j];
    if (lane == 0) { msm[w] = m; lsm[w] = l; }
    __syncthreads();

    // block merge (every thread redundantly computes M,L — cheap)
    float M = -1e30f;
#pragma unroll
    for (int ww = 0; ww < 8; ww++) M = fmaxf(M, msm[ww]);
    float L = 0.f;
    float wts[8];
#pragma unroll
    for (int ww = 0; ww < 8; ww++) {
        wts[ww] = __expf(msm[ww] - M);
        L += lsm[ww] * wts[ww];
    }

    const int cid = b * NCHUNK + c;
    if (tid == 0) { g_pm[cid] = M; g_pl[cid] = L; }

    for (int e = tid; e < ENC_; e += 256) {
        float a = 0.f;
#pragma unroll
        for (int ww = 0; ww < 8; ww++) a += accsm[ww][e] * wts[ww];
        g_pacc[(size_t)cid * ENC_ + e] = a;
    }
}

// ============================================================
// Kernel 3: finalize — merge chunk partials, write attn + sumResult
// grid = B_, block = 256
// d_out layout: attn [B,1,S] then sumResult [B,ENC]
// ============================================================
__global__ __launch_bounds__(256) void finalize(float* __restrict__ out) {
    const int b   = blockIdx.x;
    const int tid = threadIdx.x;

    // global max/denom across chunks (redundant per thread; cheap)
    float M = -1e30f;
#pragma unroll
    for (int c = 0; c < NCHUNK; c++) M = fmaxf(M, g_pm[b * NCHUNK + c]);
    float L = 0.f;
    float wts[NCHUNK];
#pragma unroll
    for (int c = 0; c < NCHUNK; c++) {
        wts[c] = __expf(g_pm[b * NCHUNK + c] - M);
        L += g_pl[b * NCHUNK + c] * wts[c];
    }
    const float invL = 1.f / L;

    // attn probabilities from stored logits
    const float* lg = g_logits + b * S_;
    float* attn_out = out + (size_t)b * S_;
    for (int s = tid; s < S_; s += 256)
        attn_out[s] = __expf(lg[s] - M) * invL;

    // sumResult
    float* sum_out = out + (size_t)B_ * S_ + (size_t)b * ENC_;
    for (int e = tid; e < ENC_; e += 256) {
        float a = 0.f;
#pragma unroll
        for (int c = 0; c < NCHUNK; c++)
            a += g_pacc[(size_t)(b * NCHUNK + c) * ENC_ + e] * wts[c];
        sum_out[e] = a * invL;
    }
}

// ============================================================
extern "C" void kernel_launch(void* const* d_in, const int* in_sizes, int n_in,
                              void* d_out, int out_size) {
    const float* dec = (const float*)d_in[0];  // [64,1,512]
    const float* enc = (const float*)d_in[1];  // [64,4096,512]
    const float* W   = (const float*)d_in[2];  // [512,512]
    float* out = (float*)d_out;

    sub_kernel<<<dim3(ENC_ / 32, B_), 256>>>(dec, W);
    attn_pass1<<<dim3(NCHUNK, B_), 256>>>(enc);
    finalize<<<B_, 256>>>(out);
}

// round 4
// speedup vs baseline: 1.1650x; 1.1650x over previous
#include <cuda_runtime.h>
#include <math.h>

// Problem constants
#define B_   64
#define S_   4096
#define ENC_ 512
#define DEC_ 512

#define NCHUNK 8                  // S chunks per batch
#define CHUNK  (S_ / NCHUNK)      // 512 rows per chunk
#define NCTOT  (B_ * NCHUNK)      // 512 total chunks

// ---- scratch (no allocations allowed; __device__ globals) ----
__device__ float g_sub[B_ * ENC_];          // dec @ W^T            (128 KB)
__device__ float g_logits[B_ * S_];         // raw attention logits (1 MB)
__device__ float g_pm[NCTOT];               // per-chunk running max
__device__ float g_pl[NCTOT];               // per-chunk running denom
__device__ float g_pacc[NCTOT * ENC_];      // per-chunk weighted-sum vec (1 MB)

// ============================================================
// Kernel 1: sub[b,e] = sum_d dec[b,d] * W[e,d]
// grid = (ENC_/32, B_/4) = (16, 16) = 256 CTAs, block = 256 (8 warps)
// Each CTA serves 4 batches with ONE read of its 32 W rows (4x less
// W traffic). Warp computes 4 e-values; per W-row load, 4 interleaved
// dot-chains (one per batch) -> high ILP, shared W bytes.
// ============================================================
__global__ __launch_bounds__(256) void sub_kernel(const float* __restrict__ dec,
                                                  const float* __restrict__ W) {
    const int et   = blockIdx.x;          // e-tile of 32
    const int b0   = blockIdx.y * 4;      // batch tile of 4
    const int tid  = threadIdx.x;
    const int w    = tid >> 5;
    const int lane = tid & 31;

    __shared__ float dsm[4][DEC_];        // 8 KB
    for (int i = tid; i < 4 * DEC_; i += 256)
        dsm[i >> 9][i & 511] = dec[(b0 + (i >> 9)) * DEC_ + (i & 511)];
    __syncthreads();

    // each lane caches its 16-float slice of all 4 batches' dec
    float4 dv[4][4];
#pragma unroll
    for (int bb = 0; bb < 4; bb++) {
        const float4* d4 = (const float4*)dsm[bb];
#pragma unroll
        for (int j = 0; j < 4; j++) dv[bb][j] = d4[lane + 32 * j];
    }

    const int e0 = et * 32 + w * 4;       // warp handles e0 .. e0+3
#pragma unroll
    for (int i = 0; i < 4; i++) {
        const int e = e0 + i;
        const float4* Wr = (const float4*)(W + (size_t)e * DEC_);
        float s0 = 0.f, s1 = 0.f, s2 = 0.f, s3 = 0.f;
#pragma unroll
        for (int j = 0; j < 4; j++) {
            const float4 wv = Wr[lane + 32 * j];
            s0 += wv.x * dv[0][j].x + wv.y * dv[0][j].y + wv.z * dv[0][j].z + wv.w * dv[0][j].w;
            s1 += wv.x * dv[1][j].x + wv.y * dv[1][j].y + wv.z * dv[1][j].z + wv.w * dv[1][j].w;
            s2 += wv.x * dv[2][j].x + wv.y * dv[2][j].y + wv.z * dv[2][j].z + wv.w * dv[2][j].w;
            s3 += wv.x * dv[3][j].x + wv.y * dv[3][j].y + wv.z * dv[3][j].z + wv.w * dv[3][j].w;
        }
#pragma unroll
        for (int o = 16; o > 0; o >>= 1) {
            s0 += __shfl_xor_sync(0xffffffffu, s0, o);
            s1 += __shfl_xor_sync(0xffffffffu, s1, o);
            s2 += __shfl_xor_sync(0xffffffffu, s2, o);
            s3 += __shfl_xor_sync(0xffffffffu, s3, o);
        }
        if (lane < 4) {
            float v = (lane == 0) ? s0 : (lane == 1) ? s1 : (lane == 2) ? s2 : s3;
            g_sub[(b0 + lane) * ENC_ + e] = v;
        }
    }
}

// ============================================================
// Kernel 2: streaming pass over encoder — logits + online softmax
// (R2 version — proven 84us / ~6.1 TB/s effective)
// grid = (NCHUNK, B_), block = 256 (8 warps, warp-per-row)
// ============================================================
__global__ __launch_bounds__(256) void attn_pass1(const float* __restrict__ enc) {
    const int c    = blockIdx.x;          // chunk index within batch
    const int b    = blockIdx.y;
    const int tid  = threadIdx.x;
    const int w    = tid >> 5;
    const int lane = tid & 31;

    __shared__ float subsm[ENC_];
    __shared__ float accsm[8][ENC_];      // 16 KB
    __shared__ float msm[8], lsm[8];

    for (int i = tid; i < ENC_; i += 256) subsm[i] = g_sub[b * ENC_ + i];
    __syncthreads();

    // cache this lane's 16-float slice of sub in registers
    float4 subr[4];
    const float4* sub4 = (const float4*)subsm;
#pragma unroll
    for (int j = 0; j < 4; j++) subr[j] = sub4[lane + 32 * j];

    float m = -1e30f;
    float l = 0.f;
    float4 acc[4];
#pragma unroll
    for (int j = 0; j < 4; j++) acc[j] = make_float4(0.f, 0.f, 0.f, 0.f);

    const int s0 = c * CHUNK;
    const float* encb = enc + (size_t)b * S_ * ENC_;

    for (int r = w; r < CHUNK; r += 8) {
        const int s = s0 + r;
        const float4* er = (const float4*)(encb + (size_t)s * ENC_);

        float4 ev[4];
#pragma unroll
        for (int j = 0; j < 4; j++) ev[j] = __ldcs(&er[lane + 32 * j]);  // streaming, 4 indep loads

        float dot = 0.f;
#pragma unroll
        for (int j = 0; j < 4; j++) {
            dot += ev[j].x * subr[j].x + ev[j].y * subr[j].y +
                   ev[j].z * subr[j].z + ev[j].w * subr[j].w;
        }
#pragma unroll
        for (int o = 16; o > 0; o >>= 1) dot += __shfl_xor_sync(0xffffffffu, dot, o);

        if (lane == 0) g_logits[b * S_ + s] = dot;

        // online softmax update (warp-uniform)
        const float mn    = fmaxf(m, dot);
        const float scale = __expf(m - mn);
        const float p     = __expf(dot - mn);
        l = l * scale + p;
#pragma unroll
        for (int j = 0; j < 4; j++) {
            acc[j].x = acc[j].x * scale + p * ev[j].x;
            acc[j].y = acc[j].y * scale + p * ev[j].y;
            acc[j].z = acc[j].z * scale + p * ev[j].z;
            acc[j].w = acc[j].w * scale + p * ev[j].w;
        }
        m = mn;
    }

    // spill warp state to smem
    float4* arow = (float4*)accsm[w];
#pragma unroll
    for (int j = 0; j < 4; j++) arow[lane + 32 * j] = acc[j];
    if (lane == 0) { msm[w] = m; lsm[w] = l; }
    __syncthreads();

    // block merge (every thread redundantly computes M,L — cheap)
    float M = -1e30f;
#pragma unroll
    for (int ww = 0; ww < 8; ww++) M = fmaxf(M, msm[ww]);
    float L = 0.f;
    float wts[8];
#pragma unroll
    for (int ww = 0; ww < 8; ww++) {
        wts[ww] = __expf(msm[ww] - M);
        L += lsm[ww] * wts[ww];
    }

    const int cid = b * NCHUNK + c;
    if (tid == 0) { g_pm[cid] = M; g_pl[cid] = L; }

    for (int e = tid; e < ENC_; e += 256) {
        float a = 0.f;
#pragma unroll
        for (int ww = 0; ww < 8; ww++) a += accsm[ww][e] * wts[ww];
        g_pacc[(size_t)cid * ENC_ + e] = a;
    }
}

// ============================================================
// Kernel 3: finalize — merge chunk partials, write attn + sumResult
// grid = B_, block = 256
// d_out layout: attn [B,1,S] then sumResult [B,ENC]
// ============================================================
__global__ __launch_bounds__(256) void finalize(float* __restrict__ out) {
    const int b   = blockIdx.x;
    const int tid = threadIdx.x;

    // global max/denom across chunks (redundant per thread; cheap)
    float M = -1e30f;
#pragma unroll
    for (int c = 0; c < NCHUNK; c++) M = fmaxf(M, g_pm[b * NCHUNK + c]);
    float L = 0.f;
    float wts[NCHUNK];
#pragma unroll
    for (int c = 0; c < NCHUNK; c++) {
        wts[c] = __expf(g_pm[b * NCHUNK + c] - M);
        L += g_pl[b * NCHUNK + c] * wts[c];
    }
    const float invL = 1.f / L;

    // attn probabilities from stored logits
    const float* lg = g_logits + b * S_;
    float* attn_out = out + (size_t)b * S_;
    for (int s = tid; s < S_; s += 256)
        attn_out[s] = __expf(lg[s] - M) * invL;

    // sumResult
    float* sum_out = out + (size_t)B_ * S_ + (size_t)b * ENC_;
    for (int e = tid; e < ENC_; e += 256) {
        float a = 0.f;
#pragma unroll
        for (int c = 0; c < NCHUNK; c++)
            a += g_pacc[(size_t)(b * NCHUNK + c) * ENC_ + e] * wts[c];
        sum_out[e] = a * invL;
    }
}

// ============================================================
extern "C" void kernel_launch(void* const* d_in, const int* in_sizes, int n_in,
                              void* d_out, int out_size) {
    const float* dec = (const float*)d_in[0];  // [64,1,512]
    const float* enc = (const float*)d_in[1];  // [64,4096,512]
    const float* W   = (const float*)d_in[2];  // [512,512]
    float* out = (float*)d_out;

    sub_kernel<<<dim3(ENC_ / 32, B_ / 4), 256>>>(dec, W);
    attn_pass1<<<dim3(NCHUNK, B_), 256>>>(enc);
    finalize<<<B_, 256>>>(out);
}